// round 6
// baseline (speedup 1.0000x reference)
#include <cuda_runtime.h>
#include <math_constants.h>

#define BB   4
#define NP   2048
#define KNN  64
#define EPS  0.005f
#define LOG_MU (-7.6246190f)   /* -log(2048) */

/* ------------ scratch (no allocations allowed) ------------ */
__device__ float g_lu[BB*NP];
__device__ float g_lv[BB*NP];
__device__ float g_sin[BB*NP];
__device__ float g_spr[BB*NP];
__device__ int   g_assign[BB*NP];
__device__ float g_avg[BB*NP];
/* materialized logK = -C/eps : [b][n][m] — 67 MB, fits in 126 MB L2 */
__device__ float g_K [(size_t)BB*NP*NP];

/* TF32 rounding (cuBLAS/CUTLASS conversion path: round-nearest-ties-away) */
__device__ __forceinline__ float tf32r(float x)
{
    float r;
    asm("cvt.rna.tf32.f32 %0, %1;" : "=f"(r) : "f"(x));
    return r;
}

/* online branchy logsumexp update (fast exp) */
#define ONL(e, mx, s) \
    { if ((e) > (mx)) { (s) = fmaf((s), __expf((mx) - (e)), 1.f); (mx) = (e); } \
      else              (s) += __expf((e) - (mx)); }

/* ------------ threefry2x32, bit-exact vs JAX ------------ */
__device__ __forceinline__ void threefry2x32(unsigned k0, unsigned k1,
                                             unsigned &x0, unsigned &x1)
{
    unsigned ks2 = k0 ^ k1 ^ 0x1BD11BDAu;
    x0 += k0; x1 += k1;
#define TFR(r) { x0 += x1; x1 = (x1 << (r)) | (x1 >> (32 - (r))); x1 ^= x0; }
    TFR(13) TFR(15) TFR(26) TFR(6)
    x0 += k1;  x1 += ks2 + 1u;
    TFR(17) TFR(29) TFR(16) TFR(24)
    x0 += ks2; x1 += k0 + 2u;
    TFR(13) TFR(15) TFR(26) TFR(6)
    x0 += k0;  x1 += k1 + 3u;
    TFR(17) TFR(29) TFR(16) TFR(24)
    x0 += k1;  x1 += ks2 + 4u;
    TFR(13) TFR(15) TFR(26) TFR(6)
    x0 += ks2; x1 += k0 + 5u;
#undef TFR
}

/* ------------ init: squared norms (full fp32) + zero duals ------------ */
__global__ void init_kernel(const float* __restrict__ preds,
                            const float* __restrict__ inputs)
{
    int i = blockIdx.x * blockDim.x + threadIdx.x;
    if (i < BB*NP) {
        float x = inputs[3*i], y = inputs[3*i+1], z = inputs[3*i+2];
        g_sin[i] = fmaf(z, z, fmaf(y, y, x*x));
        x = preds[3*i]; y = preds[3*i+1]; z = preds[3*i+2];
        g_spr[i] = fmaf(z, z, fmaf(y, y, x*x));
        g_lu[i] = 0.f;
        g_lv[i] = 0.f;
    }
}

/* ------------ build logK: g_K[b][n][m], rows = inputs, cols = preds ------------ */
__global__ void __launch_bounds__(256) build_logK(
    const float* __restrict__ rowPts,
    const float* __restrict__ innerPts)
{
    __shared__ float4 shp[NP];
    int b = blockIdx.y;
    const float* ip = innerPts + b*NP*3;
    for (int i = threadIdx.x; i < NP; i += 256)
        shp[i] = make_float4(tf32r(ip[3*i]), tf32r(ip[3*i+1]), tf32r(ip[3*i+2]),
                             g_spr[b*NP + i]);
    __syncthreads();

    int warp = threadIdx.x >> 5, lane = threadIdx.x & 31;
    int row = blockIdx.x * 8 + warp;
    const float* rp = rowPts + (b*NP + row)*3;
    float ax = tf32r(rp[0]), ay = tf32r(rp[1]), az = tf32r(rp[2]);
    float sa = g_sin[b*NP + row];
    float* orow = g_K + ((size_t)b*NP + row) * NP;

    for (int m = lane; m < NP; m += 32) {
        float4 p = shp[m];
        float dot = fmaf(az, p.z, fmaf(ay, p.y, ax * p.x));
        float d2  = fmaxf(__fadd_rn(__fadd_rn(sa, p.w), -2.0f * dot), 0.f);
        orow[m] = -(d2 / EPS);
    }
}

/* ------------ row half-step: lu[n] = LOG_MU - lse_m( g_K[n][m] + lv[m] )
   1 warp per row, float4 streaming, 4 branchy online accumulators.        */
__global__ void __launch_bounds__(256) sinkhorn_row(void)
{
    __shared__ float shl[NP];
    int b = blockIdx.y;
    for (int i = threadIdx.x; i < NP; i += 256) shl[i] = g_lv[b*NP + i];
    __syncthreads();

    int warp = threadIdx.x >> 5, lane = threadIdx.x & 31;
    int row = blockIdx.x * 8 + warp;
    const float4* M4 = (const float4*)(g_K + ((size_t)b*NP + row) * NP);
    const float4* L4 = (const float4*)shl;

    float mx0 = -CUDART_INF_F, mx1 = -CUDART_INF_F,
          mx2 = -CUDART_INF_F, mx3 = -CUDART_INF_F;
    float s0 = 0.f, s1 = 0.f, s2 = 0.f, s3 = 0.f;

#pragma unroll 4
    for (int i = 0; i < 16; i++) {
        float4 k = M4[i*32 + lane];
        float4 l = L4[i*32 + lane];
        float e;
        e = __fadd_rn(k.x, l.x); ONL(e, mx0, s0)
        e = __fadd_rn(k.y, l.y); ONL(e, mx1, s1)
        e = __fadd_rn(k.z, l.z); ONL(e, mx2, s2)
        e = __fadd_rn(k.w, l.w); ONL(e, mx3, s3)
    }

    float nm, s, mx;
    nm = fmaxf(mx0, mx1); s0 = s0 * __expf(mx0 - nm) + s1 * __expf(mx1 - nm); mx0 = nm;
    nm = fmaxf(mx2, mx3); s2 = s2 * __expf(mx2 - nm) + s3 * __expf(mx3 - nm); mx2 = nm;
    nm = fmaxf(mx0, mx2); s  = s0 * __expf(mx0 - nm) + s2 * __expf(mx2 - nm); mx = nm;

#pragma unroll
    for (int off = 16; off; off >>= 1) {
        float om = __shfl_xor_sync(0xffffffffu, mx, off);
        float os = __shfl_xor_sync(0xffffffffu, s,  off);
        nm = fmaxf(mx, om);
        s  = s * __expf(mx - nm) + os * __expf(om - nm);
        mx = nm;
    }
    if (lane == 0) {
        float r = __fadd_rn(logf(s), mx);
        g_lu[b*NP + row] = __fadd_rn(LOG_MU, -r);
    }
}

/* ------------ column half-step: lv[m] = LOG_MU - lse_n( g_K[n][m] + lu[n] )
   Tile = 32 columns. 256 threads = 8 col-threads (float4 = 4 cols each)
   x 32 row-subgroups (64 rows per thread, coalesced 128B per row segment).
   Smem merge across subgroups writes lv directly.                          */
__global__ void __launch_bounds__(256) sinkhorn_col(void)
{
    __shared__ float shlu[NP];                 /* 8 KB */
    __shared__ float smx[32][32], ssm[32][32]; /* [subgroup][col-in-tile] 4+4 KB */

    int b = blockIdx.y;
    for (int i = threadIdx.x; i < NP; i += 256) shlu[i] = g_lu[b*NP + i];
    __syncthreads();

    int t  = threadIdx.x;
    int u  = t & 7;          /* col-thread: owns cols 4u..4u+3 of the tile */
    int sg = t >> 3;         /* row subgroup 0..31 */
    int m0 = blockIdx.x * 32;
    const float4* M4 = (const float4*)(g_K + (size_t)b*NP*NP + m0) ;

    float mxa = -CUDART_INF_F, mxb = -CUDART_INF_F,
          mxc = -CUDART_INF_F, mxd = -CUDART_INF_F;
    float sa = 0.f, sb = 0.f, sc = 0.f, sd = 0.f;

#pragma unroll 4
    for (int kk = 0; kk < 64; kk++) {
        int n = sg + 32*kk;
        float4 v = M4[(size_t)n * (NP/4) + u];
        float lu = shlu[n];
        float e;
        e = __fadd_rn(v.x, lu); ONL(e, mxa, sa)
        e = __fadd_rn(v.y, lu); ONL(e, mxb, sb)
        e = __fadd_rn(v.z, lu); ONL(e, mxc, sc)
        e = __fadd_rn(v.w, lu); ONL(e, mxd, sd)
    }
    smx[sg][4*u+0] = mxa; ssm[sg][4*u+0] = sa;
    smx[sg][4*u+1] = mxb; ssm[sg][4*u+1] = sb;
    smx[sg][4*u+2] = mxc; ssm[sg][4*u+2] = sc;
    smx[sg][4*u+3] = mxd; ssm[sg][4*u+3] = sd;
    __syncthreads();

    if (t < 32) {
        float mx = -CUDART_INF_F, s = 0.f;
#pragma unroll
        for (int g = 0; g < 32; g++) {
            float m2 = smx[g][t], s2 = ssm[g][t];
            float nm = fmaxf(mx, m2);
            s = s * __expf(mx - nm) + s2 * __expf(m2 - nm);
            mx = nm;
        }
        float r = __fadd_rn(logf(s), mx);
        g_lv[b*NP + m0 + t] = __fadd_rn(LOG_MU, -r);
    }
}

/* ------------ argmax over m of g_K[n][m] + lv[m]  (lu[n] const per row) ------------ */
__global__ void __launch_bounds__(256) assign_fast(void)
{
    __shared__ float shl[NP];
    int b = blockIdx.y;
    for (int i = threadIdx.x; i < NP; i += 256) shl[i] = g_lv[b*NP + i];
    __syncthreads();

    int warp = threadIdx.x >> 5, lane = threadIdx.x & 31;
    int row = blockIdx.x * 8 + warp;
    const float4* M4 = (const float4*)(g_K + ((size_t)b*NP + row) * NP);
    const float4* L4 = (const float4*)shl;

    float best = -CUDART_INF_F;
    int   bi = 0;
    for (int i = 0; i < NP/128; i++) {
        float4 k = M4[i*32 + lane];
        float4 l = L4[i*32 + lane];
        int m0 = (i*32 + lane) * 4;
        float v;
        v = __fadd_rn(k.x, l.x); if (v > best) { best = v; bi = m0;     }
        v = __fadd_rn(k.y, l.y); if (v > best) { best = v; bi = m0 + 1; }
        v = __fadd_rn(k.z, l.z); if (v > best) { best = v; bi = m0 + 2; }
        v = __fadd_rn(k.w, l.w); if (v > best) { best = v; bi = m0 + 3; }
    }
#pragma unroll
    for (int off = 16; off; off >>= 1) {
        float ov = __shfl_xor_sync(0xffffffffu, best, off);
        int   oi = __shfl_xor_sync(0xffffffffu, bi,   off);
        if (ov > best || (ov == best && oi < bi)) { best = ov; bi = oi; }
    }
    if (lane == 0) g_assign[b*NP + row] = bi;
}

/* ------------ KNN (exact sorted top-64 via bitonic) + masked loss ------------ */
__global__ void __launch_bounds__(256) knn_loss_kernel(
    const float* __restrict__ inputs,
    const float* __restrict__ preds)
{
    __shared__ unsigned long long keys[NP];
    __shared__ float redm[KNN], redw[KNN];
    __shared__ float sh_d63;

    int row = blockIdx.x;
    int b = row >> 11, n = row & (NP - 1);
    const float* inp = inputs + b*NP*3;
    float ax = tf32r(inp[3*n]), ay = tf32r(inp[3*n+1]), az = tf32r(inp[3*n+2]);
    float sa = g_sin[b*NP + n];

    for (int m = threadIdx.x; m < NP; m += 256) {
        float bx = tf32r(inp[3*m]), by = tf32r(inp[3*m+1]), bz = tf32r(inp[3*m+2]);
        float dot = fmaf(az, bz, fmaf(ay, by, ax * bx));
        float d2  = fmaxf(__fadd_rn(__fadd_rn(sa, g_sin[b*NP + m]), -2.0f * dot), 0.f);
        keys[m] = (((unsigned long long)__float_as_uint(d2)) << 32) | (unsigned)m;
    }
    __syncthreads();

    /* ascending bitonic sort: key = (d2_bits, idx) reproduces top_k stable ties */
    for (int k = 2; k <= NP; k <<= 1) {
        for (int j = k >> 1; j > 0; j >>= 1) {
            for (int i = threadIdx.x; i < NP; i += 256) {
                int ixj = i ^ j;
                if (ixj > i) {
                    unsigned long long x = keys[i], y = keys[ixj];
                    bool up = ((i & k) == 0);
                    if ((x > y) == up) { keys[i] = y; keys[ixj] = x; }
                }
            }
            __syncthreads();
        }
    }

    int tid = threadIdx.x;
    if (tid < KNN) {
        unsigned long long key = keys[tid + 1];   /* drop self (rank 0) */
        int   idx = (int)(key & 0xffffffffull);
        float d   = __uint_as_float((unsigned)(key >> 32));

        const float C1 = (float)(0.05 * 0.05);
        const float C2 = (float)(2.0 * 0.5657 * 0.5657);
        const float C3 = (float)(0.5657 * 2.5066282746);
        float prob = expf(-(d / C1) / C2) / C3;

        /* exact JAX uniform(key(42), (4,2048,64)) */
        unsigned lin = ((unsigned)row << 6) | (unsigned)tid;
        const unsigned H = (unsigned)(BB * NP * KNN / 2);   /* 262144 */
        unsigned x0, x1, bits;
        if (lin < H) { x0 = lin;     x1 = lin + H; threefry2x32(0u, 42u, x0, x1); bits = x0; }
        else         { x0 = lin - H; x1 = lin;     threefry2x32(0u, 42u, x0, x1); bits = x1; }
        float u = __uint_as_float((bits >> 9) | 0x3f800000u) - 1.0f;
        float mask = (u < prob) ? 1.0f : 0.0f;

        int pidx = g_assign[b*NP + n];
        const float* pp = preds + (b*NP + pidx)*3;
        const float* xp = inp + idx*3;
        float dx = pp[0] - xp[0], dy = pp[1] - xp[1], dz = pp[2] - xp[2];
        float dist = fmaf(dz, dz, fmaf(dy, dy, dx * dx));

        redm[tid] = mask;
        redw[tid] = mask * dist;
        if (tid == KNN - 1) sh_d63 = dist;
    }
    __syncthreads();

    if (tid == 0) {
        float ms = 0.f, ws = 0.f;
#pragma unroll
        for (int q = 0; q < KNN; q++) { ms += redm[q]; ws += redw[q]; }
        g_avg[row] = (ms == 0.f) ? sh_d63 : (ws / ms);
    }
}

/* ------------ deterministic final reduction ------------ */
__global__ void reduce_kernel(float* __restrict__ out)
{
    __shared__ float sh[256];
    float s = 0.f;
    for (int i = threadIdx.x; i < BB*NP; i += 256) s += g_avg[i];
    sh[threadIdx.x] = s;
    __syncthreads();
    for (int off = 128; off; off >>= 1) {
        if (threadIdx.x < off) sh[threadIdx.x] += sh[threadIdx.x + off];
        __syncthreads();
    }
    if (threadIdx.x == 0) out[0] = sh[0];
}

extern "C" void kernel_launch(void* const* d_in, const int* in_sizes, int n_in,
                              void* d_out, int out_size)
{
    const float* preds  = (const float*)d_in[0];
    const float* inputs = (const float*)d_in[1];

    init_kernel<<<(BB*NP + 255) / 256, 256>>>(preds, inputs);

    dim3 g(NP / 8, BB);
    dim3 gc(NP / 32, BB);
    build_logK<<<g, 256>>>(inputs, preds);      /* g_K[n][m] */

    for (int it = 0; it < 50; ++it) {
        sinkhorn_row<<<g,  256>>>();   /* lu <- lse over rows    (reads g_K) */
        sinkhorn_col<<<gc, 256>>>();   /* lv <- lse over columns (reads g_K) */
    }
    assign_fast<<<g, 256>>>();
    knn_loss_kernel<<<BB*NP, 256>>>(inputs, preds);
    reduce_kernel<<<1, 256>>>((float*)d_out);
}

// round 11
// speedup vs baseline: 1.2556x; 1.2556x over previous
#include <cuda_runtime.h>
#include <math_constants.h>

#define BB   4
#define NP   2048
#define KNN  64
#define EPS  0.005f
#define LOG_MU (-7.6246190f)   /* -log(2048) */
#define NSEG 4                 /* row segments for the column pass */

/* ------------ scratch (no allocations allowed) ------------ */
__device__ float g_lu[BB*NP];
__device__ float g_lv[BB*NP];
__device__ float g_sin[BB*NP];
__device__ float g_spr[BB*NP];
__device__ int   g_assign[BB*NP];
__device__ float g_avg[BB*NP];
__device__ float g_pmx[BB][NSEG][NP];   /* column-pass partial max  */
__device__ float g_psm[BB][NSEG][NP];   /* column-pass partial sum  */
/* materialized logK = -C/eps : [b][n][m] — 67 MB, fits in 126 MB L2 */
__device__ float g_K [(size_t)BB*NP*NP];

/* TF32 rounding (cuBLAS/CUTLASS conversion path: round-nearest-ties-away) */
__device__ __forceinline__ float tf32r(float x)
{
    float r;
    asm("cvt.rna.tf32.f32 %0, %1;" : "=f"(r) : "f"(x));
    return r;
}

/* online branchy logsumexp update (fast exp) */
#define ONL(e, mx, s) \
    { if ((e) > (mx)) { (s) = fmaf((s), __expf((mx) - (e)), 1.f); (mx) = (e); } \
      else              (s) += __expf((e) - (mx)); }

/* ------------ threefry2x32, bit-exact vs JAX ------------ */
__device__ __forceinline__ void threefry2x32(unsigned k0, unsigned k1,
                                             unsigned &x0, unsigned &x1)
{
    unsigned ks2 = k0 ^ k1 ^ 0x1BD11BDAu;
    x0 += k0; x1 += k1;
#define TFR(r) { x0 += x1; x1 = (x1 << (r)) | (x1 >> (32 - (r))); x1 ^= x0; }
    TFR(13) TFR(15) TFR(26) TFR(6)
    x0 += k1;  x1 += ks2 + 1u;
    TFR(17) TFR(29) TFR(16) TFR(24)
    x0 += ks2; x1 += k0 + 2u;
    TFR(13) TFR(15) TFR(26) TFR(6)
    x0 += k0;  x1 += k1 + 3u;
    TFR(17) TFR(29) TFR(16) TFR(24)
    x0 += k1;  x1 += ks2 + 4u;
    TFR(13) TFR(15) TFR(26) TFR(6)
    x0 += ks2; x1 += k0 + 5u;
#undef TFR
}

/* ------------ init: squared norms (full fp32) + zero duals ------------ */
__global__ void init_kernel(const float* __restrict__ preds,
                            const float* __restrict__ inputs)
{
    int i = blockIdx.x * blockDim.x + threadIdx.x;
    if (i < BB*NP) {
        float x = inputs[3*i], y = inputs[3*i+1], z = inputs[3*i+2];
        g_sin[i] = fmaf(z, z, fmaf(y, y, x*x));
        x = preds[3*i]; y = preds[3*i+1]; z = preds[3*i+2];
        g_spr[i] = fmaf(z, z, fmaf(y, y, x*x));
        g_lu[i] = 0.f;
        g_lv[i] = 0.f;
    }
}

/* ------------ build logK: g_K[b][n][m], rows = inputs, cols = preds ------------ */
__global__ void __launch_bounds__(256) build_logK(
    const float* __restrict__ rowPts,
    const float* __restrict__ innerPts)
{
    __shared__ float4 shp[NP];
    int b = blockIdx.y;
    const float* ip = innerPts + b*NP*3;
    for (int i = threadIdx.x; i < NP; i += 256)
        shp[i] = make_float4(tf32r(ip[3*i]), tf32r(ip[3*i+1]), tf32r(ip[3*i+2]),
                             g_spr[b*NP + i]);
    __syncthreads();

    int warp = threadIdx.x >> 5, lane = threadIdx.x & 31;
    int row = blockIdx.x * 8 + warp;
    const float* rp = rowPts + (b*NP + row)*3;
    float ax = tf32r(rp[0]), ay = tf32r(rp[1]), az = tf32r(rp[2]);
    float sa = g_sin[b*NP + row];
    float* orow = g_K + ((size_t)b*NP + row) * NP;

    for (int m = lane; m < NP; m += 32) {
        float4 p = shp[m];
        float dot = fmaf(az, p.z, fmaf(ay, p.y, ax * p.x));
        float d2  = fmaxf(__fadd_rn(__fadd_rn(sa, p.w), -2.0f * dot), 0.f);
        orow[m] = -(d2 / EPS);
    }
}

/* ------------ row half-step: lu[n] = LOG_MU - lse_m( g_K[n][m] + lv[m] )
   1 warp per row, float4 streaming, 4 branchy online accumulators.        */
__global__ void __launch_bounds__(256) sinkhorn_row(void)
{
    __shared__ float shl[NP];
    int b = blockIdx.y;
    for (int i = threadIdx.x; i < NP; i += 256) shl[i] = g_lv[b*NP + i];
    __syncthreads();

    int warp = threadIdx.x >> 5, lane = threadIdx.x & 31;
    int row = blockIdx.x * 8 + warp;
    const float4* M4 = (const float4*)(g_K + ((size_t)b*NP + row) * NP);
    const float4* L4 = (const float4*)shl;

    float mx0 = -CUDART_INF_F, mx1 = -CUDART_INF_F,
          mx2 = -CUDART_INF_F, mx3 = -CUDART_INF_F;
    float s0 = 0.f, s1 = 0.f, s2 = 0.f, s3 = 0.f;

#pragma unroll
    for (int ii = 0; ii < 16; ii += 4) {
        /* batch 4 independent loads (MLP) */
        float4 k0 = M4[(ii+0)*32 + lane];
        float4 k1 = M4[(ii+1)*32 + lane];
        float4 k2 = M4[(ii+2)*32 + lane];
        float4 k3 = M4[(ii+3)*32 + lane];
        float4 l0 = L4[(ii+0)*32 + lane];
        float4 l1 = L4[(ii+1)*32 + lane];
        float4 l2 = L4[(ii+2)*32 + lane];
        float4 l3 = L4[(ii+3)*32 + lane];
        float e;
        e = __fadd_rn(k0.x, l0.x); ONL(e, mx0, s0)
        e = __fadd_rn(k0.y, l0.y); ONL(e, mx1, s1)
        e = __fadd_rn(k0.z, l0.z); ONL(e, mx2, s2)
        e = __fadd_rn(k0.w, l0.w); ONL(e, mx3, s3)
        e = __fadd_rn(k1.x, l1.x); ONL(e, mx0, s0)
        e = __fadd_rn(k1.y, l1.y); ONL(e, mx1, s1)
        e = __fadd_rn(k1.z, l1.z); ONL(e, mx2, s2)
        e = __fadd_rn(k1.w, l1.w); ONL(e, mx3, s3)
        e = __fadd_rn(k2.x, l2.x); ONL(e, mx0, s0)
        e = __fadd_rn(k2.y, l2.y); ONL(e, mx1, s1)
        e = __fadd_rn(k2.z, l2.z); ONL(e, mx2, s2)
        e = __fadd_rn(k2.w, l2.w); ONL(e, mx3, s3)
        e = __fadd_rn(k3.x, l3.x); ONL(e, mx0, s0)
        e = __fadd_rn(k3.y, l3.y); ONL(e, mx1, s1)
        e = __fadd_rn(k3.z, l3.z); ONL(e, mx2, s2)
        e = __fadd_rn(k3.w, l3.w); ONL(e, mx3, s3)
    }

    float nm, s, mx;
    nm = fmaxf(mx0, mx1); s0 = s0 * __expf(mx0 - nm) + s1 * __expf(mx1 - nm); mx0 = nm;
    nm = fmaxf(mx2, mx3); s2 = s2 * __expf(mx2 - nm) + s3 * __expf(mx3 - nm); mx2 = nm;
    nm = fmaxf(mx0, mx2); s  = s0 * __expf(mx0 - nm) + s2 * __expf(mx2 - nm); mx = nm;

#pragma unroll
    for (int off = 16; off; off >>= 1) {
        float om = __shfl_xor_sync(0xffffffffu, mx, off);
        float os = __shfl_xor_sync(0xffffffffu, s,  off);
        nm = fmaxf(mx, om);
        s  = s * __expf(mx - nm) + os * __expf(om - nm);
        mx = nm;
    }
    if (lane == 0) {
        float r = __fadd_rn(logf(s), mx);
        g_lu[b*NP + row] = __fadd_rn(LOG_MU, -r);
    }
}

/* ------------ column pass stage A: partial lse over a 32-col x 512-row tile.
   grid.x = 64 col-tiles * NSEG row-segments, grid.y = BB.
   256 threads = 8 col-threads (float4 = 4 cols) x 32 row-subgroups;
   each thread covers 16 rows with 4-wide batched loads.
   In-block smem merge -> per-(seg,col) partial (mx, s).                    */
__global__ void __launch_bounds__(256) sinkhorn_colA(void)
{
    __shared__ float shlu[512];
    __shared__ float smx[32][33], ssm[32][33];

    int b    = blockIdx.y;
    int seg  = blockIdx.x & (NSEG - 1);
    int tile = blockIdx.x >> 2;            /* 0..63 */
    int n0   = seg * 512;

    for (int i = threadIdx.x; i < 512; i += 256) shlu[i] = g_lu[b*NP + n0 + i];
    __syncthreads();

    int t = threadIdx.x;
    int u = t & 7, sg = t >> 3;
    int m0 = tile * 32;
    const float4* M4 = (const float4*)(g_K + (size_t)b*NP*NP + m0);

    float mxa = -CUDART_INF_F, mxb = -CUDART_INF_F,
          mxc = -CUDART_INF_F, mxd = -CUDART_INF_F;
    float sa = 0.f, sb = 0.f, sc = 0.f, sd = 0.f;

#pragma unroll
    for (int kk = 0; kk < 16; kk += 4) {
        /* 4 independent strided loads in flight */
        int r0 = n0 + sg + 32*(kk+0);
        int r1 = n0 + sg + 32*(kk+1);
        int r2 = n0 + sg + 32*(kk+2);
        int r3 = n0 + sg + 32*(kk+3);
        float4 v0 = M4[(size_t)r0 * (NP/4) + u];
        float4 v1 = M4[(size_t)r1 * (NP/4) + u];
        float4 v2 = M4[(size_t)r2 * (NP/4) + u];
        float4 v3 = M4[(size_t)r3 * (NP/4) + u];
        float l0 = shlu[r0 - n0], l1 = shlu[r1 - n0],
              l2 = shlu[r2 - n0], l3 = shlu[r3 - n0];
        float e;
        e = __fadd_rn(v0.x, l0); ONL(e, mxa, sa)
        e = __fadd_rn(v0.y, l0); ONL(e, mxb, sb)
        e = __fadd_rn(v0.z, l0); ONL(e, mxc, sc)
        e = __fadd_rn(v0.w, l0); ONL(e, mxd, sd)
        e = __fadd_rn(v1.x, l1); ONL(e, mxa, sa)
        e = __fadd_rn(v1.y, l1); ONL(e, mxb, sb)
        e = __fadd_rn(v1.z, l1); ONL(e, mxc, sc)
        e = __fadd_rn(v1.w, l1); ONL(e, mxd, sd)
        e = __fadd_rn(v2.x, l2); ONL(e, mxa, sa)
        e = __fadd_rn(v2.y, l2); ONL(e, mxb, sb)
        e = __fadd_rn(v2.z, l2); ONL(e, mxc, sc)
        e = __fadd_rn(v2.w, l2); ONL(e, mxd, sd)
        e = __fadd_rn(v3.x, l3); ONL(e, mxa, sa)
        e = __fadd_rn(v3.y, l3); ONL(e, mxb, sb)
        e = __fadd_rn(v3.z, l3); ONL(e, mxc, sc)
        e = __fadd_rn(v3.w, l3); ONL(e, mxd, sd)
    }
    smx[sg][4*u+0] = mxa; ssm[sg][4*u+0] = sa;
    smx[sg][4*u+1] = mxb; ssm[sg][4*u+1] = sb;
    smx[sg][4*u+2] = mxc; ssm[sg][4*u+2] = sc;
    smx[sg][4*u+3] = mxd; ssm[sg][4*u+3] = sd;
    __syncthreads();

    if (t < 32) {
        float mx = -CUDART_INF_F, s = 0.f;
#pragma unroll
        for (int g = 0; g < 32; g++) {
            float m2 = smx[g][t], s2 = ssm[g][t];
            float nm = fmaxf(mx, m2);
            s = s * __expf(mx - nm) + s2 * __expf(m2 - nm);
            mx = nm;
        }
        g_pmx[b][seg][m0 + t] = mx;
        g_psm[b][seg][m0 + t] = s;
    }
}

/* ------------ column pass stage B: merge NSEG partials -> lv ------------ */
__global__ void __launch_bounds__(256) sinkhorn_colB(void)
{
    int i = blockIdx.x * 256 + threadIdx.x;
    if (i < BB*NP) {
        int b = i >> 11, m = i & (NP - 1);
        float mx = -CUDART_INF_F, s = 0.f;
#pragma unroll
        for (int seg = 0; seg < NSEG; seg++) {
            float m2 = g_pmx[b][seg][m], s2 = g_psm[b][seg][m];
            float nm = fmaxf(mx, m2);
            s = s * __expf(mx - nm) + s2 * __expf(m2 - nm);
            mx = nm;
        }
        float r = __fadd_rn(logf(s), mx);
        g_lv[i] = __fadd_rn(LOG_MU, -r);
    }
}

/* ------------ argmax over m of g_K[n][m] + lv[m]  (lu[n] const per row) ------------ */
__global__ void __launch_bounds__(256) assign_fast(void)
{
    __shared__ float shl[NP];
    int b = blockIdx.y;
    for (int i = threadIdx.x; i < NP; i += 256) shl[i] = g_lv[b*NP + i];
    __syncthreads();

    int warp = threadIdx.x >> 5, lane = threadIdx.x & 31;
    int row = blockIdx.x * 8 + warp;
    const float4* M4 = (const float4*)(g_K + ((size_t)b*NP + row) * NP);
    const float4* L4 = (const float4*)shl;

    float best = -CUDART_INF_F;
    int   bi = 0;
    for (int i = 0; i < NP/128; i++) {
        float4 k = M4[i*32 + lane];
        float4 l = L4[i*32 + lane];
        int m0 = (i*32 + lane) * 4;
        float v;
        v = __fadd_rn(k.x, l.x); if (v > best) { best = v; bi = m0;     }
        v = __fadd_rn(k.y, l.y); if (v > best) { best = v; bi = m0 + 1; }
        v = __fadd_rn(k.z, l.z); if (v > best) { best = v; bi = m0 + 2; }
        v = __fadd_rn(k.w, l.w); if (v > best) { best = v; bi = m0 + 3; }
    }
#pragma unroll
    for (int off = 16; off; off >>= 1) {
        float ov = __shfl_xor_sync(0xffffffffu, best, off);
        int   oi = __shfl_xor_sync(0xffffffffu, bi,   off);
        if (ov > best || (ov == best && oi < bi)) { best = ov; bi = oi; }
    }
    if (lane == 0) g_assign[b*NP + row] = bi;
}

/* ------------ KNN (exact sorted top-64 via bitonic) + masked loss ------------ */
__global__ void __launch_bounds__(256) knn_loss_kernel(
    const float* __restrict__ inputs,
    const float* __restrict__ preds)
{
    __shared__ unsigned long long keys[NP];
    __shared__ float redm[KNN], redw[KNN];
    __shared__ float sh_d63;

    int row = blockIdx.x;
    int b = row >> 11, n = row & (NP - 1);
    const float* inp = inputs + b*NP*3;
    float ax = tf32r(inp[3*n]), ay = tf32r(inp[3*n+1]), az = tf32r(inp[3*n+2]);
    float sa = g_sin[b*NP + n];

    for (int m = threadIdx.x; m < NP; m += 256) {
        float bx = tf32r(inp[3*m]), by = tf32r(inp[3*m+1]), bz = tf32r(inp[3*m+2]);
        float dot = fmaf(az, bz, fmaf(ay, by, ax * bx));
        float d2  = fmaxf(__fadd_rn(__fadd_rn(sa, g_sin[b*NP + m]), -2.0f * dot), 0.f);
        keys[m] = (((unsigned long long)__float_as_uint(d2)) << 32) | (unsigned)m;
    }
    __syncthreads();

    /* ascending bitonic sort: key = (d2_bits, idx) reproduces top_k stable ties */
    for (int k = 2; k <= NP; k <<= 1) {
        for (int j = k >> 1; j > 0; j >>= 1) {
            for (int i = threadIdx.x; i < NP; i += 256) {
                int ixj = i ^ j;
                if (ixj > i) {
                    unsigned long long x = keys[i], y = keys[ixj];
                    bool up = ((i & k) == 0);
                    if ((x > y) == up) { keys[i] = y; keys[ixj] = x; }
                }
            }
            __syncthreads();
        }
    }

    int tid = threadIdx.x;
    if (tid < KNN) {
        unsigned long long key = keys[tid + 1];   /* drop self (rank 0) */
        int   idx = (int)(key & 0xffffffffull);
        float d   = __uint_as_float((unsigned)(key >> 32));

        const float C1 = (float)(0.05 * 0.05);
        const float C2 = (float)(2.0 * 0.5657 * 0.5657);
        const float C3 = (float)(0.5657 * 2.5066282746);
        float prob = expf(-(d / C1) / C2) / C3;

        /* exact JAX uniform(key(42), (4,2048,64)) */
        unsigned lin = ((unsigned)row << 6) | (unsigned)tid;
        const unsigned H = (unsigned)(BB * NP * KNN / 2);   /* 262144 */
        unsigned x0, x1, bits;
        if (lin < H) { x0 = lin;     x1 = lin + H; threefry2x32(0u, 42u, x0, x1); bits = x0; }
        else         { x0 = lin - H; x1 = lin;     threefry2x32(0u, 42u, x0, x1); bits = x1; }
        float u = __uint_as_float((bits >> 9) | 0x3f800000u) - 1.0f;
        float mask = (u < prob) ? 1.0f : 0.0f;

        int pidx = g_assign[b*NP + n];
        const float* pp = preds + (b*NP + pidx)*3;
        const float* xp = inp + idx*3;
        float dx = pp[0] - xp[0], dy = pp[1] - xp[1], dz = pp[2] - xp[2];
        float dist = fmaf(dz, dz, fmaf(dy, dy, dx * dx));

        redm[tid] = mask;
        redw[tid] = mask * dist;
        if (tid == KNN - 1) sh_d63 = dist;
    }
    __syncthreads();

    if (tid == 0) {
        float ms = 0.f, ws = 0.f;
#pragma unroll
        for (int q = 0; q < KNN; q++) { ms += redm[q]; ws += redw[q]; }
        g_avg[row] = (ms == 0.f) ? sh_d63 : (ws / ms);
    }
}

/* ------------ deterministic final reduction ------------ */
__global__ void reduce_kernel(float* __restrict__ out)
{
    __shared__ float sh[256];
    float s = 0.f;
    for (int i = threadIdx.x; i < BB*NP; i += 256) s += g_avg[i];
    sh[threadIdx.x] = s;
    __syncthreads();
    for (int off = 128; off; off >>= 1) {
        if (threadIdx.x < off) sh[threadIdx.x] += sh[threadIdx.x + off];
        __syncthreads();
    }
    if (threadIdx.x == 0) out[0] = sh[0];
}

extern "C" void kernel_launch(void* const* d_in, const int* in_sizes, int n_in,
                              void* d_out, int out_size)
{
    const float* preds  = (const float*)d_in[0];
    const float* inputs = (const float*)d_in[1];

    init_kernel<<<(BB*NP + 255) / 256, 256>>>(preds, inputs);

    dim3 g(NP / 8, BB);
    dim3 gA(64 * NSEG, BB);
    build_logK<<<g, 256>>>(inputs, preds);      /* g_K[n][m] */

    for (int it = 0; it < 50; ++it) {
        sinkhorn_row <<<g,  256>>>();   /* lu <- lse over rows  */
        sinkhorn_colA<<<gA, 256>>>();   /* column partials      */
        sinkhorn_colB<<<32, 256>>>();   /* merge -> lv          */
    }
    assign_fast<<<g, 256>>>();
    knn_loss_kernel<<<BB*NP, 256>>>(inputs, preds);
    reduce_kernel<<<1, 256>>>((float*)d_out);
}